// round 8
// baseline (speedup 1.0000x reference)
#include <cuda_runtime.h>
#include <cuda_bf16.h>

#define EMB 32
#define NUM_RADIAL 16
#define Z_CAP 96           // dataset NUM_Z = 95
#define EPB 128            // edges per block == threads
#define RPAD 36            // table/SO row stride (floats), bank-spread
#define AST 20             // rbf A-staging row stride (halfs)
#define KP1 20             // sB1 k-stride (halfs)
#define KP2 36             // sB2 k-stride (halfs)

typedef unsigned int uint;

__constant__ float c_Wr[NUM_RADIAL * EMB];   // W_rbf [16][32]
__constant__ float c_W3[EMB * EMB];          // W_dense rows 64..95 [32][32]
__constant__ float c_br[EMB];

// Padded precomputed tables (emb1 with b_dense folded; emb2)
__device__ __align__(16) float g_pad[2 * Z_CAP * RPAD];

__global__ void precompute_emb_kernel(const float* __restrict__ emb_table,
                                      const float* __restrict__ W_dense,
                                      const float* __restrict__ b_dense,
                                      int num_z)
{
    int z = blockIdx.x;
    int j = threadIdx.x;
    if (z >= Z_CAP || j >= EMB) return;

    float acc1 = 0.0f, acc2 = 0.0f;
    if (z < num_z) {
        acc1 = b_dense[j];
#pragma unroll
        for (int k = 0; k < EMB; ++k) {
            float e = emb_table[z * EMB + k];
            acc1 += e * W_dense[k * EMB + j];
            acc2 += e * W_dense[(EMB + k) * EMB + j];
        }
    }
    g_pad[z * RPAD + j] = acc1;
    g_pad[Z_CAP * RPAD + z * RPAD + j] = acc2;
    if (j < RPAD - EMB) {
        g_pad[z * RPAD + EMB + j] = 0.0f;
        g_pad[Z_CAP * RPAD + z * RPAD + EMB + j] = 0.0f;
    }
}

// ---- helpers ----
__device__ __forceinline__ uint bf16pair(float lo, float hi) {
    uint r;
    asm("cvt.rn.bf16x2.f32 %0, %1, %2;" : "=r"(r) : "f"(hi), "f"(lo));
    return r;
}
__device__ __forceinline__ void split2(float a, float b, uint& h, uint& l) {
    h = bf16pair(a, b);
    float ha = __uint_as_float(h << 16);
    float hb = __uint_as_float(h & 0xffff0000u);
    l = bf16pair(a - ha, b - hb);
}
__device__ __forceinline__ unsigned short bf16_1(float x) {
    __nv_bfloat16 h = __float2bfloat16(x);
    return __bfloat16_as_ushort(h);
}
__device__ __forceinline__ void mma16816(float* d, const uint* a, const uint* b) {
    asm("mma.sync.aligned.m16n8k16.row.col.f32.bf16.bf16.f32 "
        "{%0,%1,%2,%3}, {%4,%5,%6,%7}, {%8,%9}, {%0,%1,%2,%3};"
        : "+f"(d[0]), "+f"(d[1]), "+f"(d[2]), "+f"(d[3])
        : "r"(a[0]), "r"(a[1]), "r"(a[2]), "r"(a[3]), "r"(b[0]), "r"(b[1]));
}
__device__ __forceinline__ float silu_f(float s) {
    float z = __expf(-s);
    return __fdividef(s, 1.0f + z);
}

__global__ __launch_bounds__(EPB)
void dimenet_edge_kernel(const float* __restrict__ d_ij,
                         const float* __restrict__ frequencies,
                         const int*   __restrict__ Z,
                         const int*   __restrict__ idnb_i,
                         const int*   __restrict__ idnb_j,
                         float* __restrict__ out,
                         int E, int N)
{
    __shared__ __align__(16) float sT[2 * Z_CAP * RPAD];            // 27.6 KB (tables -> SO reuse)
    __shared__ __align__(16) unsigned short sArbf[256 * AST];       // 10.2 KB (rbf hi rows 0..127, lo 128..255)
    __shared__ __align__(8)  unsigned short sB1[2 * 32 * KP1];      // 2.5 KB
    __shared__ __align__(8)  unsigned short sB2[2 * 32 * KP2];      // 4.6 KB
    __shared__ int sZi[EPB], sZj[EPB];

    const int tid = threadIdx.x;
    const int e   = blockIdx.x * EPB + tid;
    const int es  = (e < E) ? e : (E - 1);

    // ---- table copy gmem -> smem (coalesced) ----
    {
        const float4* src = reinterpret_cast<const float4*>(g_pad);
        float4* dst = reinterpret_cast<float4*>(sT);
        const int n4 = (2 * Z_CAP * RPAD) / 4;     // 1728
#pragma unroll
        for (int i = 0; i < (n4 + EPB - 1) / EPB; ++i) {
            int idx = i * EPB + tid;
            if (idx < n4) dst[idx] = __ldg(&src[idx]);
        }
    }
    // ---- build bf16-split B matrices (transposed [n][k]) ----
#pragma unroll
    for (int i = 0; i < 4; ++i) {                    // 512 entries of W_rbf
        int idx = i * EPB + tid;
        int k = idx >> 5, n = idx & 31;
        float w = c_Wr[idx];
        unsigned short h = bf16_1(w);
        float hw = __uint_as_float((uint)h << 16);
        sB1[n * KP1 + k] = h;
        sB1[(32 + n) * KP1 + k] = bf16_1(w - hw);
    }
#pragma unroll
    for (int i = 0; i < 8; ++i) {                    // 1024 entries of W3
        int idx = i * EPB + tid;
        int k = idx >> 5, n = idx & 31;
        float w = c_W3[idx];
        unsigned short h = bf16_1(w);
        float hw = __uint_as_float((uint)h << 16);
        sB2[n * KP2 + k] = h;
        sB2[(32 + n) * KP2 + k] = bf16_1(w - hw);
    }

    // ---- per-edge scalars + z indices ----
    {
        int ni = idnb_i[es], nj = idnb_j[es];
        ni = min(max(ni, 0), N - 1);  nj = min(max(nj, 0), N - 1);
        int zi = Z[ni], zj = Z[nj];
        sZi[tid] = min(max(zi, 0), Z_CAP - 1);
        sZj[tid] = min(max(zj, 0), Z_CAP - 1);
    }

    // ---- rbf basis (envelope p=6, Chebyshev) + bf16 split + staging ----
    {
        const float d = d_ij[es];
        const float f0 = frequencies[0];
        const float x = d * 0.2f;
        const float x2 = x * x;
        const float x4 = x2 * x2;
        const float x5 = x4 * x;
        float env = 1.0f / x + x5 * (-28.0f + x * (48.0f - 21.0f * x));
        env = (x < 1.0f) ? env : 0.0f;

        float s, c0;
        sincosf(f0 * x, &s, &c0);
        const float twoc = 2.0f * c0;

        float rbf[NUM_RADIAL];
        float sm1 = 0.0f, sk = s;
#pragma unroll
        for (int k = 0; k < NUM_RADIAL; ++k) {
            rbf[k] = env * sk;
            float sp1 = twoc * sk - sm1;
            sm1 = sk; sk = sp1;
        }
#pragma unroll
        for (int c4 = 0; c4 < 4; ++c4) {
            uint h0, l0, h1, l1;
            split2(rbf[4*c4 + 0], rbf[4*c4 + 1], h0, l0);
            split2(rbf[4*c4 + 2], rbf[4*c4 + 3], h1, l1);
            *reinterpret_cast<uint2*>(&sArbf[tid * AST + c4 * 4])         = make_uint2(h0, h1);
            *reinterpret_cast<uint2*>(&sArbf[(128 + tid) * AST + c4 * 4]) = make_uint2(l0, l1);
        }
    }
    __syncthreads();

    const int lane = tid & 31;
    const int warp = tid >> 5;
    const int g  = lane >> 2;
    const int tg = lane & 3;
    const int rbase = warp * 32;

    // ---- GEMM1: u = rbf @ W_rbf + b_rbf  (M=32, N=32, K=16) ----
    uint A1h[2][4], A1l[2][4];
#pragma unroll
    for (int mt = 0; mt < 2; ++mt) {
        int r = rbase + mt * 16 + g;
        A1h[mt][0] = *reinterpret_cast<const uint*>(&sArbf[r * AST + tg * 2]);
        A1h[mt][1] = *reinterpret_cast<const uint*>(&sArbf[(r + 8) * AST + tg * 2]);
        A1h[mt][2] = *reinterpret_cast<const uint*>(&sArbf[r * AST + tg * 2 + 8]);
        A1h[mt][3] = *reinterpret_cast<const uint*>(&sArbf[(r + 8) * AST + tg * 2 + 8]);
        int rl = 128 + r;
        A1l[mt][0] = *reinterpret_cast<const uint*>(&sArbf[rl * AST + tg * 2]);
        A1l[mt][1] = *reinterpret_cast<const uint*>(&sArbf[(rl + 8) * AST + tg * 2]);
        A1l[mt][2] = *reinterpret_cast<const uint*>(&sArbf[rl * AST + tg * 2 + 8]);
        A1l[mt][3] = *reinterpret_cast<const uint*>(&sArbf[(rl + 8) * AST + tg * 2 + 8]);
    }
    float acc1[2][4][4];
#pragma unroll
    for (int nt = 0; nt < 4; ++nt) {
        int n = nt * 8 + g;
        uint bh[2], bl[2];
        bh[0] = *reinterpret_cast<const uint*>(&sB1[n * KP1 + tg * 2]);
        bh[1] = *reinterpret_cast<const uint*>(&sB1[n * KP1 + tg * 2 + 8]);
        bl[0] = *reinterpret_cast<const uint*>(&sB1[(32 + n) * KP1 + tg * 2]);
        bl[1] = *reinterpret_cast<const uint*>(&sB1[(32 + n) * KP1 + tg * 2 + 8]);
        float b0 = c_br[nt * 8 + tg * 2];
        float b1 = c_br[nt * 8 + tg * 2 + 1];
#pragma unroll
        for (int mt = 0; mt < 2; ++mt) {
            acc1[mt][nt][0] = b0; acc1[mt][nt][1] = b1;
            acc1[mt][nt][2] = b0; acc1[mt][nt][3] = b1;
            mma16816(acc1[mt][nt], A1h[mt], bh);
            mma16816(acc1[mt][nt], A1h[mt], bl);
            mma16816(acc1[mt][nt], A1l[mt], bh);
        }
    }

    // ---- silu(u) -> t, convert to GEMM2 A fragments in registers ----
#pragma unroll
    for (int mt = 0; mt < 2; ++mt)
#pragma unroll
        for (int nt = 0; nt < 4; ++nt)
#pragma unroll
            for (int q = 0; q < 4; ++q)
                acc1[mt][nt][q] = silu_f(acc1[mt][nt][q]);

    uint A2h[2][2][4], A2l[2][2][4];
#pragma unroll
    for (int mt = 0; mt < 2; ++mt)
#pragma unroll
        for (int kt = 0; kt < 2; ++kt) {
            split2(acc1[mt][2*kt][0],   acc1[mt][2*kt][1],   A2h[mt][kt][0], A2l[mt][kt][0]);
            split2(acc1[mt][2*kt][2],   acc1[mt][2*kt][3],   A2h[mt][kt][1], A2l[mt][kt][1]);
            split2(acc1[mt][2*kt+1][0], acc1[mt][2*kt+1][1], A2h[mt][kt][2], A2l[mt][kt][2]);
            split2(acc1[mt][2*kt+1][2], acc1[mt][2*kt+1][3], A2h[mt][kt][3], A2l[mt][kt][3]);
        }

    // ---- GEMM2 accumulator init: emb1[zi] + emb2[zj] in fragment layout ----
    float acc2[2][4][4];
#pragma unroll
    for (int mt = 0; mt < 2; ++mt)
#pragma unroll
        for (int nt = 0; nt < 4; ++nt) {
            int r1 = rbase + mt * 16 + g, r2 = r1 + 8;
            int c = nt * 8 + tg * 2;
            float2 p1 = *reinterpret_cast<const float2*>(&sT[sZi[r1] * RPAD + c]);
            float2 q1 = *reinterpret_cast<const float2*>(&sT[Z_CAP * RPAD + sZj[r1] * RPAD + c]);
            float2 p2 = *reinterpret_cast<const float2*>(&sT[sZi[r2] * RPAD + c]);
            float2 q2 = *reinterpret_cast<const float2*>(&sT[Z_CAP * RPAD + sZj[r2] * RPAD + c]);
            acc2[mt][nt][0] = p1.x + q1.x;
            acc2[mt][nt][1] = p1.y + q1.y;
            acc2[mt][nt][2] = p2.x + q2.x;
            acc2[mt][nt][3] = p2.y + q2.y;
        }

    // ---- GEMM2: acc2 += t @ W3  (M=32, N=32, K=32) ----
#pragma unroll
    for (int kt = 0; kt < 2; ++kt) {
#pragma unroll
        for (int nt = 0; nt < 4; ++nt) {
            int n = nt * 8 + g;
            uint bh[2], bl[2];
            bh[0] = *reinterpret_cast<const uint*>(&sB2[n * KP2 + kt * 16 + tg * 2]);
            bh[1] = *reinterpret_cast<const uint*>(&sB2[n * KP2 + kt * 16 + tg * 2 + 8]);
            bl[0] = *reinterpret_cast<const uint*>(&sB2[(32 + n) * KP2 + kt * 16 + tg * 2]);
            bl[1] = *reinterpret_cast<const uint*>(&sB2[(32 + n) * KP2 + kt * 16 + tg * 2 + 8]);
#pragma unroll
            for (int mt = 0; mt < 2; ++mt) {
                mma16816(acc2[mt][nt], A2h[mt][kt], bh);
                mma16816(acc2[mt][nt], A2h[mt][kt], bl);
                mma16816(acc2[mt][nt], A2l[mt][kt], bh);
            }
        }
    }

    __syncthreads();   // all emb reads done; reuse sT as SO staging

    // ---- final silu -> SO staging (padded rows) ----
#pragma unroll
    for (int mt = 0; mt < 2; ++mt)
#pragma unroll
        for (int nt = 0; nt < 4; ++nt) {
            int r1 = rbase + mt * 16 + g, r2 = r1 + 8;
            int c = nt * 8 + tg * 2;
            float2 v1, v2;
            v1.x = silu_f(acc2[mt][nt][0]); v1.y = silu_f(acc2[mt][nt][1]);
            v2.x = silu_f(acc2[mt][nt][2]); v2.y = silu_f(acc2[mt][nt][3]);
            *reinterpret_cast<float2*>(&sT[r1 * RPAD + c]) = v1;
            *reinterpret_cast<float2*>(&sT[r2 * RPAD + c]) = v2;
        }
    __syncthreads();

    // ---- coalesced stores ----
    float4* out4 = reinterpret_cast<float4*>(out);
    const long long base4 = (long long)blockIdx.x * (EPB * (EMB / 4));
#pragma unroll
    for (int i = 0; i < 8; ++i) {
        int fidx = i * EPB + tid;
        int el = fidx >> 3;
        int c  = fidx & 7;
        float4 v = *reinterpret_cast<const float4*>(&sT[el * RPAD + c * 4]);
        int eg = blockIdx.x * EPB + el;
        if (eg < E) out4[base4 + fidx] = v;
    }
}

extern "C" void kernel_launch(void* const* d_in, const int* in_sizes, int n_in,
                              void* d_out, int out_size)
{
    const float* d_dij   = (const float*)d_in[0];
    const float* d_freq  = (const float*)d_in[1];
    const float* d_emb   = (const float*)d_in[2];
    const float* d_Wrbf  = (const float*)d_in[3];
    const float* d_brbf  = (const float*)d_in[4];
    const float* d_Wd    = (const float*)d_in[5];
    const float* d_bd    = (const float*)d_in[6];
    const int*   d_Z     = (const int*)d_in[7];
    const int*   d_i     = (const int*)d_in[8];
    const int*   d_j     = (const int*)d_in[9];
    float*       out     = (float*)d_out;

    const int E = in_sizes[0];
    const int N = in_sizes[7];
    int num_z   = in_sizes[2] / EMB;
    if (num_z > Z_CAP) num_z = Z_CAP;
    if (num_z < 1)     num_z = 1;

    cudaMemcpyToSymbolAsync(c_Wr, d_Wrbf, NUM_RADIAL * EMB * sizeof(float), 0,
                            cudaMemcpyDeviceToDevice);
    cudaMemcpyToSymbolAsync(c_W3, d_Wd + (size_t)(2 * EMB) * EMB,
                            EMB * EMB * sizeof(float), 0,
                            cudaMemcpyDeviceToDevice);
    cudaMemcpyToSymbolAsync(c_br, d_brbf, EMB * sizeof(float), 0,
                            cudaMemcpyDeviceToDevice);

    precompute_emb_kernel<<<Z_CAP, EMB>>>(d_emb, d_Wd, d_bd, num_z);

    const int blocks = (E + EPB - 1) / EPB;
    dimenet_edge_kernel<<<blocks, EPB>>>(d_dij, d_freq, d_Z, d_i, d_j, out, E, N);
}

// round 9
// speedup vs baseline: 1.3869x; 1.3869x over previous
#include <cuda_runtime.h>
#include <cuda_bf16.h>

#define EMB 32
#define NUM_RADIAL 16
#define Z_CAP 96           // dataset NUM_Z = 95
#define EPB 256            // edges per block == threads
#define RPAD 36            // padded row stride (floats): 36 % 32 = 4 -> bank spread
#define TBL_FLOATS (2 * Z_CAP * RPAD)    // 6912 floats = 27.6 KB
#define SO_FLOATS  (EPB * RPAD)          // 9216 floats = 36.9 KB
#define SMEM_FLOATS (SO_FLOATS)          // union buffer (SO is larger)

typedef unsigned long long ull;

__constant__ float c_Wr[NUM_RADIAL * EMB];   // 2 KB
__constant__ float c_W3[EMB * EMB];          // 4 KB (rows 64..95 of W_dense)
__constant__ float c_br[EMB];

// Padded precomputed tables, contiguous for linear block copy:
//   g_pad[z*RPAD + j]              = emb1[z][j] (b_dense folded)
//   g_pad[Z_CAP*RPAD + z*RPAD + j] = emb2[z][j]
__device__ __align__(16) float g_pad[TBL_FLOATS];

__global__ void precompute_emb_kernel(const float* __restrict__ emb_table,
                                      const float* __restrict__ W_dense,
                                      const float* __restrict__ b_dense,
                                      int num_z)
{
    int z = blockIdx.x;
    int j = threadIdx.x;
    if (z >= Z_CAP || j >= EMB) return;

    float acc1 = 0.0f, acc2 = 0.0f;
    if (z < num_z) {
        acc1 = b_dense[j];
#pragma unroll
        for (int k = 0; k < EMB; ++k) {
            float e = emb_table[z * EMB + k];
            acc1 += e * W_dense[k * EMB + j];
            acc2 += e * W_dense[(EMB + k) * EMB + j];
        }
    }
    g_pad[z * RPAD + j] = acc1;
    g_pad[Z_CAP * RPAD + z * RPAD + j] = acc2;
    if (j < RPAD - EMB) {
        g_pad[z * RPAD + EMB + j] = 0.0f;
        g_pad[Z_CAP * RPAD + z * RPAD + EMB + j] = 0.0f;
    }
}

__device__ __forceinline__ ull pk2(float lo, float hi) {
    ull r; asm("mov.b64 %0, {%1, %2};" : "=l"(r) : "f"(lo), "f"(hi)); return r;
}
__device__ __forceinline__ void upk2(ull v, float& lo, float& hi) {
    asm("mov.b64 {%0, %1}, %2;" : "=f"(lo), "=f"(hi) : "l"(v));
}
__device__ __forceinline__ ull ffma2(ull a, ull b, ull c) {
    ull d; asm("fma.rn.f32x2 %0, %1, %2, %3;" : "=l"(d) : "l"(a), "l"(b), "l"(c)); return d;
}
__device__ __forceinline__ float silu_f(float s) {
    float z = __expf(-s);
    return __fdividef(s, 1.0f + z);
}

__global__ __launch_bounds__(EPB)
void dimenet_edge_kernel(const float* __restrict__ d_ij,
                         const float* __restrict__ frequencies,
                         const int*   __restrict__ Z,
                         const int*   __restrict__ idnb_i,
                         const int*   __restrict__ idnb_j,
                         float* __restrict__ out,
                         int E, int N)
{
    // Union: first the two gather tables (TBL_FLOATS), later SO staging (SO_FLOATS).
    __shared__ __align__(16) float sT[SMEM_FLOATS];

    const int tid = threadIdx.x;
    const int e   = blockIdx.x * EPB + tid;
    const int es  = (e < E) ? e : (E - 1);

    // ---- scalar inputs (early, overlaps table copy) ----
    const float d = d_ij[es];
    int ni = idnb_i[es], nj = idnb_j[es];
    ni = min(max(ni, 0), N - 1);  nj = min(max(nj, 0), N - 1);
    int zi = Z[ni], zj = Z[nj];
    zi = min(max(zi, 0), Z_CAP - 1);
    zj = min(max(zj, 0), Z_CAP - 1);
    const float f0 = frequencies[0];

    // ---- linear table copy: gmem -> smem (coalesced, amortized over 256 edges) ----
    {
        const float4* src = reinterpret_cast<const float4*>(g_pad);
        float4* dst = reinterpret_cast<float4*>(sT);
        const int n4 = TBL_FLOATS / 4;                 // 1728
#pragma unroll
        for (int i = 0; i < (n4 + EPB - 1) / EPB; ++i) {   // 7 iters
            int idx = i * EPB + tid;
            if (idx < n4) dst[idx] = __ldg(&src[idx]);
        }
    }

    // ---- rbf basis (envelope p=6, Chebyshev) — overlaps copy latency ----
    const float x = d * 0.2f;
    const float x2 = x * x;
    const float x4 = x2 * x2;
    const float x5 = x4 * x;
    float env = 1.0f / x + x5 * (-28.0f + x * (48.0f - 21.0f * x));
    env = (x < 1.0f) ? env : 0.0f;

    float s, c0;
    sincosf(f0 * x, &s, &c0);
    const float twoc = 2.0f * c0;

    float rbf[NUM_RADIAL];
    {
        float sm1 = 0.0f, sk = s;
#pragma unroll
        for (int k = 0; k < NUM_RADIAL; ++k) {
            rbf[k] = env * sk;
            float sp1 = twoc * sk - sm1;
            sm1 = sk; sk = sp1;
        }
    }

    // ---- t = silu(rbf @ W_rbf + b_rbf)  (constant weights -> no L1) ----
    ull tp[EMB / 2];
    {
        const ull* br2 = reinterpret_cast<const ull*>(c_br);
#pragma unroll
        for (int j2 = 0; j2 < EMB / 2; ++j2) tp[j2] = br2[j2];
#pragma unroll
        for (int k = 0; k < NUM_RADIAL; ++k) {
            const ull rb = pk2(rbf[k], rbf[k]);
            const ull* w2 = reinterpret_cast<const ull*>(c_Wr + k * EMB);
#pragma unroll
            for (int j2 = 0; j2 < EMB / 2; ++j2)
                tp[j2] = ffma2(rb, w2[j2], tp[j2]);
        }
    }
    float t[EMB];
#pragma unroll
    for (int j2 = 0; j2 < EMB / 2; ++j2) {
        float a, b;
        upk2(tp[j2], a, b);
        t[2*j2] = silu_f(a); t[2*j2+1] = silu_f(b);
    }

    __syncthreads();   // tables resident

    // ---- acc = emb1[zi] + emb2[zj] from padded smem rows ----
    ull acc[EMB / 2];
    {
        const float4* r1 = reinterpret_cast<const float4*>(sT + zi * RPAD);
        const float4* r2 = reinterpret_cast<const float4*>(sT + Z_CAP * RPAD + zj * RPAD);
#pragma unroll
        for (int c = 0; c < 8; ++c) {
            float4 a = r1[c];
            float4 b = r2[c];
            acc[2*c    ] = pk2(a.x + b.x, a.y + b.y);
            acc[2*c + 1] = pk2(a.z + b.z, a.w + b.w);
        }
    }

    // ---- acc += t @ W3 ----
#pragma unroll
    for (int k = 0; k < EMB; ++k) {
        const ull tb = pk2(t[k], t[k]);
        const ull* w2 = reinterpret_cast<const ull*>(c_W3 + k * EMB);
#pragma unroll
        for (int j2 = 0; j2 < EMB / 2; ++j2)
            acc[j2] = ffma2(tb, w2[j2], acc[j2]);
    }

    __syncthreads();   // all table reads done; reuse sT as SO staging

    // ---- stage silu(acc) at SO[tid][c] (padded rows, conflict-spread) ----
    {
        float4* so = reinterpret_cast<float4*>(sT + tid * RPAD);
#pragma unroll
        for (int c = 0; c < 8; ++c) {
            float a, b, cc, dd;
            upk2(acc[2*c], a, b); upk2(acc[2*c + 1], cc, dd);
            float4 v;
            v.x = silu_f(a); v.y = silu_f(b); v.z = silu_f(cc); v.w = silu_f(dd);
            so[c] = v;
        }
    }
    __syncthreads();

    // ---- coalesced stores: lanes write consecutive float4 ----
    float4* out4 = reinterpret_cast<float4*>(out);
    const long long base4 = (long long)blockIdx.x * (EPB * (EMB / 4));
#pragma unroll
    for (int i = 0; i < 8; ++i) {
        int fidx = i * EPB + tid;        // 0..2047 chunk index within block
        int el = fidx >> 3;              // local edge
        int c  = fidx & 7;               // chunk
        float4 v = *reinterpret_cast<const float4*>(sT + el * RPAD + c * 4);
        int eg = blockIdx.x * EPB + el;
        if (eg < E) out4[base4 + fidx] = v;
    }
}

extern "C" void kernel_launch(void* const* d_in, const int* in_sizes, int n_in,
                              void* d_out, int out_size)
{
    const float* d_dij   = (const float*)d_in[0];
    const float* d_freq  = (const float*)d_in[1];
    const float* d_emb   = (const float*)d_in[2];
    const float* d_Wrbf  = (const float*)d_in[3];
    const float* d_brbf  = (const float*)d_in[4];
    const float* d_Wd    = (const float*)d_in[5];
    const float* d_bd    = (const float*)d_in[6];
    const int*   d_Z     = (const int*)d_in[7];
    const int*   d_i     = (const int*)d_in[8];
    const int*   d_j     = (const int*)d_in[9];
    float*       out     = (float*)d_out;

    const int E = in_sizes[0];
    const int N = in_sizes[7];
    int num_z   = in_sizes[2] / EMB;
    if (num_z > Z_CAP) num_z = Z_CAP;
    if (num_z < 1)     num_z = 1;

    cudaMemcpyToSymbolAsync(c_Wr, d_Wrbf, NUM_RADIAL * EMB * sizeof(float), 0,
                            cudaMemcpyDeviceToDevice);
    cudaMemcpyToSymbolAsync(c_W3, d_Wd + (size_t)(2 * EMB) * EMB,
                            EMB * EMB * sizeof(float), 0,
                            cudaMemcpyDeviceToDevice);
    cudaMemcpyToSymbolAsync(c_br, d_brbf, EMB * sizeof(float), 0,
                            cudaMemcpyDeviceToDevice);

    precompute_emb_kernel<<<Z_CAP, EMB>>>(d_emb, d_Wd, d_bd, num_z);

    const int blocks = (E + EPB - 1) / EPB;
    dimenet_edge_kernel<<<blocks, EPB>>>(d_dij, d_freq, d_Z, d_i, d_j, out, E, N);
}

// round 10
// speedup vs baseline: 1.5568x; 1.1225x over previous
#include <cuda_runtime.h>
#include <cuda_bf16.h>

#define EMB 32
#define NUM_RADIAL 16
#define Z_CAP 96           // dataset NUM_Z = 95
#define EPB 256            // edges per block == threads
#define RPAD 36            // padded row stride (floats): 36 % 32 = 4 -> bank spread
#define TBL_FLOATS (2 * Z_CAP * RPAD)    // 6912 floats = 27.6 KB
// SO staging for a HALF-wave (128 edges) fits inside the table buffer:
// 128 * RPAD = 4608 floats = 18.4 KB  <=  TBL_FLOATS

typedef unsigned long long ull;

__constant__ float c_Wr[NUM_RADIAL * EMB];   // 2 KB
__constant__ float c_W3[EMB * EMB];          // 4 KB (rows 64..95 of W_dense)
__constant__ float c_br[EMB];

__device__ __align__(16) float g_pad[TBL_FLOATS];

__global__ void precompute_emb_kernel(const float* __restrict__ emb_table,
                                      const float* __restrict__ W_dense,
                                      const float* __restrict__ b_dense,
                                      int num_z)
{
    int z = blockIdx.x;
    int j = threadIdx.x;
    if (z >= Z_CAP || j >= EMB) return;

    float acc1 = 0.0f, acc2 = 0.0f;
    if (z < num_z) {
        acc1 = b_dense[j];
#pragma unroll
        for (int k = 0; k < EMB; ++k) {
            float e = emb_table[z * EMB + k];
            acc1 += e * W_dense[k * EMB + j];
            acc2 += e * W_dense[(EMB + k) * EMB + j];
        }
    }
    g_pad[z * RPAD + j] = acc1;
    g_pad[Z_CAP * RPAD + z * RPAD + j] = acc2;
    if (j < RPAD - EMB) {
        g_pad[z * RPAD + EMB + j] = 0.0f;
        g_pad[Z_CAP * RPAD + z * RPAD + EMB + j] = 0.0f;
    }
}

__device__ __forceinline__ ull pk2(float lo, float hi) {
    ull r; asm("mov.b64 %0, {%1, %2};" : "=l"(r) : "f"(lo), "f"(hi)); return r;
}
__device__ __forceinline__ void upk2(ull v, float& lo, float& hi) {
    asm("mov.b64 {%0, %1}, %2;" : "=f"(lo), "=f"(hi) : "l"(v));
}
__device__ __forceinline__ ull ffma2(ull a, ull b, ull c) {
    ull d; asm("fma.rn.f32x2 %0, %1, %2, %3;" : "=l"(d) : "l"(a), "l"(b), "l"(c)); return d;
}
__device__ __forceinline__ float silu_f(float s) {
    float z = __expf(-s);
    return __fdividef(s, 1.0f + z);
}

__global__ __launch_bounds__(EPB, 3)
void dimenet_edge_kernel(const float* __restrict__ d_ij,
                         const float* __restrict__ frequencies,
                         const int*   __restrict__ Z,
                         const int*   __restrict__ idnb_i,
                         const int*   __restrict__ idnb_j,
                         float* __restrict__ out,
                         int E, int N)
{
    // Union: gather tables first; after gathers complete, reused as SO staging
    // for two half-waves of 128 edges each.
    __shared__ __align__(16) float sT[TBL_FLOATS];

    const int tid = threadIdx.x;
    const int e   = blockIdx.x * EPB + tid;
    const int es  = (e < E) ? e : (E - 1);

    // ---- scalar inputs (early) ----
    const float d = d_ij[es];
    int ni = idnb_i[es], nj = idnb_j[es];
    ni = min(max(ni, 0), N - 1);  nj = min(max(nj, 0), N - 1);
    int zi = Z[ni], zj = Z[nj];
    zi = min(max(zi, 0), Z_CAP - 1);
    zj = min(max(zj, 0), Z_CAP - 1);
    const float f0 = frequencies[0];

    // ---- linear table copy gmem -> smem (coalesced; amortized over 256 edges) ----
    {
        const float4* src = reinterpret_cast<const float4*>(g_pad);
        float4* dst = reinterpret_cast<float4*>(sT);
        const int n4 = TBL_FLOATS / 4;                 // 1728
#pragma unroll
        for (int i = 0; i < (n4 + EPB - 1) / EPB; ++i) {   // 7 iters
            int idx = i * EPB + tid;
            if (idx < n4) dst[idx] = __ldg(&src[idx]);
        }
    }

    // ---- rbf basis (envelope p=6, Chebyshev) — overlaps copy latency ----
    const float x = d * 0.2f;
    const float x2 = x * x;
    const float x4 = x2 * x2;
    const float x5 = x4 * x;
    float env = 1.0f / x + x5 * (-28.0f + x * (48.0f - 21.0f * x));
    env = (x < 1.0f) ? env : 0.0f;

    float s, c0;
    sincosf(f0 * x, &s, &c0);
    const float twoc = 2.0f * c0;

    float rbf[NUM_RADIAL];
    {
        float sm1 = 0.0f, sk = s;
#pragma unroll
        for (int k = 0; k < NUM_RADIAL; ++k) {
            rbf[k] = env * sk;
            float sp1 = twoc * sk - sm1;
            sm1 = sk; sk = sp1;
        }
    }

    // ---- t = silu(rbf @ W_rbf + b_rbf)  (constant weights -> no L1) ----
    ull tp[EMB / 2];
    {
        const ull* br2 = reinterpret_cast<const ull*>(c_br);
#pragma unroll
        for (int j2 = 0; j2 < EMB / 2; ++j2) tp[j2] = br2[j2];
#pragma unroll
        for (int k = 0; k < NUM_RADIAL; ++k) {
            const ull rb = pk2(rbf[k], rbf[k]);
            const ull* w2 = reinterpret_cast<const ull*>(c_Wr + k * EMB);
#pragma unroll
            for (int j2 = 0; j2 < EMB / 2; ++j2)
                tp[j2] = ffma2(rb, w2[j2], tp[j2]);
        }
    }
    float t[EMB];
#pragma unroll
    for (int j2 = 0; j2 < EMB / 2; ++j2) {
        float a, b;
        upk2(tp[j2], a, b);
        t[2*j2] = silu_f(a); t[2*j2+1] = silu_f(b);
    }

    __syncthreads();   // tables resident

    // ---- acc = emb1[zi] + emb2[zj] from padded smem rows ----
    ull acc[EMB / 2];
    {
        const float4* r1 = reinterpret_cast<const float4*>(sT + zi * RPAD);
        const float4* r2 = reinterpret_cast<const float4*>(sT + Z_CAP * RPAD + zj * RPAD);
#pragma unroll
        for (int c = 0; c < 8; ++c) {
            float4 a = r1[c];
            float4 b = r2[c];
            acc[2*c    ] = pk2(a.x + b.x, a.y + b.y);
            acc[2*c + 1] = pk2(a.z + b.z, a.w + b.w);
        }
    }

    // ---- acc += t @ W3 ----
#pragma unroll
    for (int k = 0; k < EMB; ++k) {
        const ull tb = pk2(t[k], t[k]);
        const ull* w2 = reinterpret_cast<const ull*>(c_W3 + k * EMB);
#pragma unroll
        for (int j2 = 0; j2 < EMB / 2; ++j2)
            acc[j2] = ffma2(tb, w2[j2], acc[j2]);
    }

    // ---- final silu into registers ----
    float o[EMB];
#pragma unroll
    for (int j2 = 0; j2 < EMB / 2; ++j2) {
        float a, b;
        upk2(acc[j2], a, b);
        o[2*j2] = silu_f(a); o[2*j2+1] = silu_f(b);
    }

    __syncthreads();   // all table reads done; reuse sT as SO staging

    // ---- two half-waves: stage 128 edges, store coalesced, repeat ----
    float4* out4 = reinterpret_cast<float4*>(out);
    const long long base4 = (long long)blockIdx.x * (EPB * (EMB / 4));

#pragma unroll
    for (int w = 0; w < 2; ++w) {
        // stage: threads [w*128, w*128+128) write their 32 floats
        if ((tid >> 7) == w) {
            float4* so = reinterpret_cast<float4*>(sT + (tid & 127) * RPAD);
#pragma unroll
            for (int c = 0; c < 8; ++c)
                so[c] = make_float4(o[4*c], o[4*c+1], o[4*c+2], o[4*c+3]);
        }
        __syncthreads();
        // store: all 256 threads push 1024 float4 (128 edges * 8 chunks)
#pragma unroll
        for (int i = 0; i < 4; ++i) {
            int fidx = i * EPB + tid;            // 0..1023
            int el = fidx >> 3;                  // local edge in half-wave
            int c  = fidx & 7;
            float4 v = *reinterpret_cast<const float4*>(sT + el * RPAD + c * 4);
            int eg = blockIdx.x * EPB + w * 128 + el;
            if (eg < E) out4[base4 + w * 1024 + fidx] = v;
        }
        __syncthreads();
    }
}

extern "C" void kernel_launch(void* const* d_in, const int* in_sizes, int n_in,
                              void* d_out, int out_size)
{
    const float* d_dij   = (const float*)d_in[0];
    const float* d_freq  = (const float*)d_in[1];
    const float* d_emb   = (const float*)d_in[2];
    const float* d_Wrbf  = (const float*)d_in[3];
    const float* d_brbf  = (const float*)d_in[4];
    const float* d_Wd    = (const float*)d_in[5];
    const float* d_bd    = (const float*)d_in[6];
    const int*   d_Z     = (const int*)d_in[7];
    const int*   d_i     = (const int*)d_in[8];
    const int*   d_j     = (const int*)d_in[9];
    float*       out     = (float*)d_out;

    const int E = in_sizes[0];
    const int N = in_sizes[7];
    int num_z   = in_sizes[2] / EMB;
    if (num_z > Z_CAP) num_z = Z_CAP;
    if (num_z < 1)     num_z = 1;

    cudaMemcpyToSymbolAsync(c_Wr, d_Wrbf, NUM_RADIAL * EMB * sizeof(float), 0,
                            cudaMemcpyDeviceToDevice);
    cudaMemcpyToSymbolAsync(c_W3, d_Wd + (size_t)(2 * EMB) * EMB,
                            EMB * EMB * sizeof(float), 0,
                            cudaMemcpyDeviceToDevice);
    cudaMemcpyToSymbolAsync(c_br, d_brbf, EMB * sizeof(float), 0,
                            cudaMemcpyDeviceToDevice);

    precompute_emb_kernel<<<Z_CAP, EMB>>>(d_emb, d_Wd, d_bd, num_z);

    const int blocks = (E + EPB - 1) / EPB;
    dimenet_edge_kernel<<<blocks, EPB>>>(d_dij, d_freq, d_Z, d_i, d_j, out, E, N);
}

// round 11
// speedup vs baseline: 1.7776x; 1.1418x over previous
#include <cuda_runtime.h>
#include <cuda_bf16.h>

#define EMB 32
#define NUM_RADIAL 16
#define Z_CAP 96           // dataset NUM_Z = 95
#define EPB 256            // edges per block == threads
#define RPAD 36            // padded row stride (floats): 36 % 32 = 4 -> bank spread
#define TBL_FLOATS (2 * Z_CAP * RPAD)    // 6912 floats = 27.6 KB

typedef unsigned long long ull;

__constant__ __align__(16) float c_Wr[NUM_RADIAL * EMB];   // 2 KB
__constant__ __align__(16) float c_W3[EMB * EMB];          // 4 KB (rows 64..95 of W_dense)
__constant__ __align__(16) float c_br[EMB];

__device__ __align__(16) float g_pad[TBL_FLOATS];

__global__ void precompute_emb_kernel(const float* __restrict__ emb_table,
                                      const float* __restrict__ W_dense,
                                      const float* __restrict__ b_dense,
                                      int num_z)
{
    int z = blockIdx.x;
    int j = threadIdx.x;
    if (z >= Z_CAP || j >= EMB) return;

    float acc1 = 0.0f, acc2 = 0.0f;
    if (z < num_z) {
        acc1 = b_dense[j];
#pragma unroll
        for (int k = 0; k < EMB; ++k) {
            float e = emb_table[z * EMB + k];
            acc1 += e * W_dense[k * EMB + j];
            acc2 += e * W_dense[(EMB + k) * EMB + j];
        }
    }
    g_pad[z * RPAD + j] = acc1;
    g_pad[Z_CAP * RPAD + z * RPAD + j] = acc2;
    if (j < RPAD - EMB) {
        g_pad[z * RPAD + EMB + j] = 0.0f;
        g_pad[Z_CAP * RPAD + z * RPAD + EMB + j] = 0.0f;
    }
}

__device__ __forceinline__ ull pk2(float lo, float hi) {
    ull r; asm("mov.b64 %0, {%1, %2};" : "=l"(r) : "f"(lo), "f"(hi)); return r;
}
__device__ __forceinline__ void upk2(ull v, float& lo, float& hi) {
    asm("mov.b64 {%0, %1}, %2;" : "=f"(lo), "=f"(hi) : "l"(v));
}
__device__ __forceinline__ ull ffma2(ull a, ull b, ull c) {
    ull d; asm("fma.rn.f32x2 %0, %1, %2, %3;" : "=l"(d) : "l"(a), "l"(b), "l"(c)); return d;
}
// silu via single MUFU.TANH: s * (0.5*tanh(0.5*s) + 0.5)
__device__ __forceinline__ float silu_f(float s) {
    float th;
    asm("tanh.approx.f32 %0, %1;" : "=f"(th) : "f"(0.5f * s));
    return s * fmaf(0.5f, th, 0.5f);
}

__global__ __launch_bounds__(EPB, 3)
void dimenet_edge_kernel(const float* __restrict__ d_ij,
                         const float* __restrict__ frequencies,
                         const int*   __restrict__ Z,
                         const int*   __restrict__ idnb_i,
                         const int*   __restrict__ idnb_j,
                         float* __restrict__ out,
                         int E, int N)
{
    // Union: gather tables first; later reused as SO staging (two half-waves).
    __shared__ __align__(16) float sT[TBL_FLOATS];

    const int tid = threadIdx.x;
    const int e   = blockIdx.x * EPB + tid;
    const int es  = (e < E) ? e : (E - 1);

    // ---- scalar inputs (early) ----
    const float d = d_ij[es];
    int ni = idnb_i[es], nj = idnb_j[es];
    ni = min(max(ni, 0), N - 1);  nj = min(max(nj, 0), N - 1);
    int zi = Z[ni], zj = Z[nj];
    zi = min(max(zi, 0), Z_CAP - 1);
    zj = min(max(zj, 0), Z_CAP - 1);
    const float f0 = frequencies[0];

    // ---- linear table copy gmem -> smem (coalesced) ----
    {
        const float4* src = reinterpret_cast<const float4*>(g_pad);
        float4* dst = reinterpret_cast<float4*>(sT);
        const int n4 = TBL_FLOATS / 4;                 // 1728
#pragma unroll
        for (int i = 0; i < (n4 + EPB - 1) / EPB; ++i) {
            int idx = i * EPB + tid;
            if (idx < n4) dst[idx] = __ldg(&src[idx]);
        }
    }

    // ---- rbf basis (envelope p=6, Chebyshev) ----
    const float x = d * 0.2f;
    const float x2 = x * x;
    const float x4 = x2 * x2;
    const float x5 = x4 * x;
    float env = 1.0f / x + x5 * (-28.0f + x * (48.0f - 21.0f * x));
    env = (x < 1.0f) ? env : 0.0f;

    float s, c0;
    sincosf(f0 * x, &s, &c0);
    const float twoc = 2.0f * c0;

    float rbf[NUM_RADIAL];
    {
        float sm1 = 0.0f, sk = s;
#pragma unroll
        for (int k = 0; k < NUM_RADIAL; ++k) {
            rbf[k] = env * sk;
            float sp1 = twoc * sk - sm1;
            sm1 = sk; sk = sp1;
        }
    }

    // ---- t = silu(rbf @ W_rbf + b_rbf); constants via 16B LDCU ----
    ull tp[EMB / 2];
    {
        const ulonglong2* br4 = reinterpret_cast<const ulonglong2*>(c_br);
#pragma unroll
        for (int q = 0; q < EMB / 4; ++q) {
            ulonglong2 b = br4[q];
            tp[2*q] = b.x; tp[2*q + 1] = b.y;
        }
#pragma unroll
        for (int k = 0; k < NUM_RADIAL; ++k) {
            const ull rb = pk2(rbf[k], rbf[k]);
            const ulonglong2* w4 = reinterpret_cast<const ulonglong2*>(c_Wr + k * EMB);
#pragma unroll
            for (int q = 0; q < EMB / 4; ++q) {
                ulonglong2 ww = w4[q];
                tp[2*q    ] = ffma2(rb, ww.x, tp[2*q    ]);
                tp[2*q + 1] = ffma2(rb, ww.y, tp[2*q + 1]);
            }
        }
    }
    float t[EMB];
#pragma unroll
    for (int j2 = 0; j2 < EMB / 2; ++j2) {
        float a, b;
        upk2(tp[j2], a, b);
        t[2*j2] = silu_f(a); t[2*j2+1] = silu_f(b);
    }

    __syncthreads();   // tables resident

    // ---- acc = emb1[zi] + emb2[zj] from padded smem rows ----
    ull acc[EMB / 2];
    {
        const float4* r1 = reinterpret_cast<const float4*>(sT + zi * RPAD);
        const float4* r2 = reinterpret_cast<const float4*>(sT + Z_CAP * RPAD + zj * RPAD);
#pragma unroll
        for (int c = 0; c < 8; ++c) {
            float4 a = r1[c];
            float4 b = r2[c];
            acc[2*c    ] = pk2(a.x + b.x, a.y + b.y);
            acc[2*c + 1] = pk2(a.z + b.z, a.w + b.w);
        }
    }

    // ---- acc += t @ W3 (16B constant loads) ----
#pragma unroll
    for (int k = 0; k < EMB; ++k) {
        const ull tb = pk2(t[k], t[k]);
        const ulonglong2* w4 = reinterpret_cast<const ulonglong2*>(c_W3 + k * EMB);
#pragma unroll
        for (int q = 0; q < EMB / 4; ++q) {
            ulonglong2 ww = w4[q];
            acc[2*q    ] = ffma2(tb, ww.x, acc[2*q    ]);
            acc[2*q + 1] = ffma2(tb, ww.y, acc[2*q + 1]);
        }
    }

    // ---- final silu into registers ----
    float o[EMB];
#pragma unroll
    for (int j2 = 0; j2 < EMB / 2; ++j2) {
        float a, b;
        upk2(acc[j2], a, b);
        o[2*j2] = silu_f(a); o[2*j2+1] = silu_f(b);
    }

    __syncthreads();   // table reads done; reuse sT as SO staging

    // ---- two half-waves: stage 128 edges, store coalesced ----
    float4* out4 = reinterpret_cast<float4*>(out);
    const long long base4 = (long long)blockIdx.x * (EPB * (EMB / 4));

#pragma unroll
    for (int w = 0; w < 2; ++w) {
        if ((tid >> 7) == w) {
            float4* so = reinterpret_cast<float4*>(sT + (tid & 127) * RPAD);
#pragma unroll
            for (int c = 0; c < 8; ++c)
                so[c] = make_float4(o[4*c], o[4*c+1], o[4*c+2], o[4*c+3]);
        }
        __syncthreads();
#pragma unroll
        for (int i = 0; i < 4; ++i) {
            int fidx = i * EPB + tid;            // 0..1023
            int el = fidx >> 3;
            int c  = fidx & 7;
            float4 v = *reinterpret_cast<const float4*>(sT + el * RPAD + c * 4);
            int eg = blockIdx.x * EPB + w * 128 + el;
            if (eg < E) out4[base4 + w * 1024 + fidx] = v;
        }
        __syncthreads();
    }
}

extern "C" void kernel_launch(void* const* d_in, const int* in_sizes, int n_in,
                              void* d_out, int out_size)
{
    const float* d_dij   = (const float*)d_in[0];
    const float* d_freq  = (const float*)d_in[1];
    const float* d_emb   = (const float*)d_in[2];
    const float* d_Wrbf  = (const float*)d_in[3];
    const float* d_brbf  = (const float*)d_in[4];
    const float* d_Wd    = (const float*)d_in[5];
    const float* d_bd    = (const float*)d_in[6];
    const int*   d_Z     = (const int*)d_in[7];
    const int*   d_i     = (const int*)d_in[8];
    const int*   d_j     = (const int*)d_in[9];
    float*       out     = (float*)d_out;

    const int E = in_sizes[0];
    const int N = in_sizes[7];
    int num_z   = in_sizes[2] / EMB;
    if (num_z > Z_CAP) num_z = Z_CAP;
    if (num_z < 1)     num_z = 1;

    cudaMemcpyToSymbolAsync(c_Wr, d_Wrbf, NUM_RADIAL * EMB * sizeof(float), 0,
                            cudaMemcpyDeviceToDevice);
    cudaMemcpyToSymbolAsync(c_W3, d_Wd + (size_t)(2 * EMB) * EMB,
                            EMB * EMB * sizeof(float), 0,
                            cudaMemcpyDeviceToDevice);
    cudaMemcpyToSymbolAsync(c_br, d_brbf, EMB * sizeof(float), 0,
                            cudaMemcpyDeviceToDevice);

    precompute_emb_kernel<<<Z_CAP, EMB>>>(d_emb, d_Wd, d_bd, num_z);

    const int blocks = (E + EPB - 1) / EPB;
    dimenet_edge_kernel<<<blocks, EPB>>>(d_dij, d_freq, d_Z, d_i, d_j, out, E, N);
}